// round 3
// baseline (speedup 1.0000x reference)
#include <cuda_runtime.h>

#define BATCH 128
#define CH 1024
#define KSPLIT 8
#define NTILE 32
#define KTILE 32
#define KCHUNK (CH / KSPLIT)   // 128

// Scratch (allocation-free rule: __device__ globals)
static __device__ float g_h[BATCH * CH];               // 512 KB: h = visual + crossed
static __device__ float g_part[KSPLIT * BATCH * CH];   // 4 MB: split-K partials

__device__ __forceinline__ float ex2f(float x) {
    float y;
    asm("ex2.approx.ftz.f32 %0, %1;" : "=f"(y) : "f"(x));
    return y;
}

// ---------------------------------------------------------------------------
// Kernel A: per-row softmax cross attention.
// crossed[b,i] = (sum_j e^{t_i v_j} v_j) / (sum_j e^{t_i v_j});  h = v_i + crossed
// v pre-scaled by log2(e) in smem so EX2 is fed directly; recover via *ln2.
// grid = BATCH*4 blocks of 256 threads; each thread owns one (b,i) row.
// ---------------------------------------------------------------------------
__global__ __launch_bounds__(256) void cross_kernel(
    const float* __restrict__ visual, const float* __restrict__ tactile)
{
    __shared__ __align__(16) float vl[CH];
    const int b = blockIdx.x >> 2;
    const int chunk = blockIdx.x & 3;
    const float LOG2E = 1.4426950408889634f;
    const float LN2   = 0.6931471805599453f;

    const float* vb = visual + b * CH;
#pragma unroll
    for (int k = 0; k < 4; k++) {
        int idx = threadIdx.x + k * 256;
        vl[idx] = vb[idx] * LOG2E;
    }
    __syncthreads();

    const int i = chunk * 256 + threadIdx.x;
    const float t = tactile[b * CH + i];

    float sum0 = 0.f, sum1 = 0.f;
    float dot0 = 0.f, dot1 = 0.f;
    const float4* vl4 = reinterpret_cast<const float4*>(vl);
#pragma unroll 4
    for (int j = 0; j < CH / 4; j++) {
        float4 v = vl4[j];
        float e0 = ex2f(t * v.x);
        float e1 = ex2f(t * v.y);
        float e2 = ex2f(t * v.z);
        float e3 = ex2f(t * v.w);
        sum0 += e0 + e2;
        sum1 += e1 + e3;
        dot0 = fmaf(e0, v.x, dot0);
        dot1 = fmaf(e1, v.y, dot1);
        dot0 = fmaf(e2, v.z, dot0);
        dot1 = fmaf(e3, v.w, dot1);
    }
    float sum = sum0 + sum1;
    float dot = dot0 + dot1;                 // = log2e * sum_j e_j v_j
    float h = (vl[i] + __fdividef(dot, sum)) * LN2;  // vl[i]*ln2 = v_i
    g_h[b * CH + i] = h;
}

// ---------------------------------------------------------------------------
// Kernel B: split-K GEMM  y_part[kz][b,o] = sum_{k in chunk} Wc[o,k] * h[b,k]
// Wc[o,k] = conv_w[(o*CH + k)*9 + 4]  (center tap of 3x3 on 1x1 spatial).
// grid = 32 n-tiles x 8 k-splits = 256 CTAs, 256 threads, 4x4 register tile.
// ---------------------------------------------------------------------------
__global__ __launch_bounds__(256) void gemm_kernel(const float* __restrict__ conv_w)
{
    __shared__ __align__(16) float sh[KTILE][BATCH + 4];   // [32][132]
    __shared__ __align__(16) float sw[KTILE][NTILE + 4];   // [32][36]

    const int nb = blockIdx.x & 31;
    const int kz = blockIdx.x >> 5;
    const int nbase = nb * NTILE;
    const int kbase = kz * KCHUNK;

    const int tx = threadIdx.x & 7;    // o group (8 x 4)
    const int ty = threadIdx.x >> 3;   // b group (32 x 4)

    float acc[4][4] = {};

    for (int kk = 0; kk < KCHUNK; kk += KTILE) {
        // load h tile: 128 b x 32 k, transposed into smem [k][b]
#pragma unroll
        for (int it = 0; it < 16; it++) {
            int l = threadIdx.x + it * 256;
            int bb = l >> 5, c = l & 31;
            sh[c][bb] = g_h[bb * CH + kbase + kk + c];
        }
        // load W tile: 32 o x 32 k (center tap, stride 9)
#pragma unroll
        for (int it = 0; it < 4; it++) {
            int l = threadIdx.x + it * 256;
            int o = l >> 5, c = l & 31;
            sw[c][o] = conv_w[((nbase + o) * CH + (kbase + kk + c)) * 9 + 4];
        }
        __syncthreads();

#pragma unroll
        for (int k = 0; k < KTILE; k++) {
            float4 hv = *reinterpret_cast<const float4*>(&sh[k][ty * 4]);
            float4 wv = *reinterpret_cast<const float4*>(&sw[k][tx * 4]);
            float hb[4] = {hv.x, hv.y, hv.z, hv.w};
            float wo[4] = {wv.x, wv.y, wv.z, wv.w};
#pragma unroll
            for (int bi = 0; bi < 4; bi++)
#pragma unroll
                for (int oi = 0; oi < 4; oi++)
                    acc[bi][oi] = fmaf(hb[bi], wo[oi], acc[bi][oi]);
        }
        __syncthreads();
    }

    float* outp = g_part + kz * (BATCH * CH);
#pragma unroll
    for (int bi = 0; bi < 4; bi++) {
        float4 r = make_float4(acc[bi][0], acc[bi][1], acc[bi][2], acc[bi][3]);
        *reinterpret_cast<float4*>(&outp[(ty * 4 + bi) * CH + nbase + tx * 4]) = r;
    }
}

// ---------------------------------------------------------------------------
// Kernel C: reduce split-K partials + conv bias + BN (eval) + LeakyReLU(0.1)
// ---------------------------------------------------------------------------
__global__ __launch_bounds__(256) void final_kernel(
    const float* __restrict__ cb, const float* __restrict__ gamma,
    const float* __restrict__ beta, const float* __restrict__ mean,
    const float* __restrict__ var, float* __restrict__ out)
{
    const int idx = blockIdx.x * 256 + threadIdx.x;
    const int o = idx & (CH - 1);
    float s = 0.f;
#pragma unroll
    for (int kz = 0; kz < KSPLIT; kz++)
        s += g_part[kz * (BATCH * CH) + idx];
    float A = gamma[o] * rsqrtf(var[o] + 1e-5f);
    float v = (s + cb[o] - mean[o]) * A + beta[o];
    out[idx] = v > 0.f ? v : 0.1f * v;
}

extern "C" void kernel_launch(void* const* d_in, const int* in_sizes, int n_in,
                              void* d_out, int out_size)
{
    const float* visual  = (const float*)d_in[0];
    const float* tactile = (const float*)d_in[1];
    const float* conv_w  = (const float*)d_in[2];
    const float* conv_b  = (const float*)d_in[3];
    const float* gamma   = (const float*)d_in[4];
    const float* beta    = (const float*)d_in[5];
    const float* mean    = (const float*)d_in[6];
    const float* var     = (const float*)d_in[7];
    float* out = (float*)d_out;

    cross_kernel<<<BATCH * 4, 256>>>(visual, tactile);
    gemm_kernel<<<32 * KSPLIT, 256>>>(conv_w);
    final_kernel<<<(BATCH * CH) / 256, 256>>>(conv_b, gamma, beta, mean, var, out);
}